// round 17
// baseline (speedup 1.0000x reference)
#include <cuda_runtime.h>
#include <cuda_fp16.h>
#include <cstdint>

#define Bv 16
#define Cv 64
#define Hv 128
#define Wv 128
#define HCv 64
#define NROWS 2048
#define GRID 148

// ---- smem map (bytes) ----
// W resident: 3 x 32KB at 0 (built in-kernel from fp32 wgt)
// XBUF: 2 x 24KB (96-k super-chunks) at 98304 .. 147456
// GATES fp16 at 147456: [m(256)][138 halves] (stride 276B = 69 words == 5 mod 32)
// PS (scan partials, fp32 pairs) at 218112 (4KB)
#define XBUF_B 98304
#define GATE_B 147456
#define GROW_B 276
#define PS_B   218112
#define SMEM_BYTES 222208

extern __shared__ uint32_t smw[];

__device__ __forceinline__ uint32_t smem_u32(const void* p) {
    uint32_t a;
    asm("{ .reg .u64 t; cvta.to.shared.u64 t, %1; cvt.u32.u64 %0, t; }"
        : "=r"(a) : "l"(p));
    return a;
}

__device__ __forceinline__ float tanh_f(float x) {
    float y;
    asm("tanh.approx.f32 %0, %1;" : "=f"(y) : "f"(x));
    return y;
}
__device__ __forceinline__ float sigmoid_f(float x) {
    return fmaf(tanh_f(0.5f * x), 0.5f, 0.5f);
}

// fp16-accumulator MMA
__device__ __forceinline__ void mma_f16acc(uint32_t* c, const uint32_t* a,
                                           uint32_t b0, uint32_t b1) {
    asm volatile(
        "mma.sync.aligned.m16n8k16.row.col.f16.f16.f16.f16 "
        "{%0,%1}, {%2,%3,%4,%5}, {%6,%7}, {%0,%1};\n"
        : "+r"(c[0]), "+r"(c[1])
        : "r"(a[0]), "r"(a[1]), "r"(a[2]), "r"(a[3]), "r"(b0), "r"(b1));
}

#define LDM4(R, addr) \
    asm volatile("ldmatrix.sync.aligned.m8n8.x4.shared.b16 {%0,%1,%2,%3}, [%4];" \
        : "=r"((R)[0]), "=r"((R)[1]), "=r"((R)[2]), "=r"((R)[3]) : "r"(addr))
#define LDM4T(R, addr) \
    asm volatile("ldmatrix.sync.aligned.m8n8.x4.trans.shared.b16 {%0,%1,%2,%3}, [%4];" \
        : "=r"((R)[0]), "=r"((R)[1]), "=r"((R)[2]), "=r"((R)[3]) : "r"(addr))

__device__ __forceinline__ void sts32(uint32_t a, uint32_t v) {
    asm volatile("st.shared.u32 [%0], %1;" :: "r"(a), "r"(v) : "memory");
}
__device__ __forceinline__ uint32_t lds32(uint32_t a) {
    uint32_t v;
    asm volatile("ld.shared.u32 %0, [%1];" : "=r"(v) : "r"(a));
    return v;
}
__device__ __forceinline__ float2 h2f2(uint32_t w) {
    return __half22float2(*reinterpret_cast<__half2*>(&w));
}
__device__ __forceinline__ uint32_t packh2(float lo, float hi) {
    uint32_t w;
    asm("cvt.rn.f16x2.f32 %0, %1, %2;" : "=r"(w) : "f"(hi), "f"(lo));
    return w;
}

// ---------------------------------------------------------------- persistent fused kernel
// 148 CTAs (1/SM), 512 threads = 16 warps (4m x 4n), warp tile 64m x 32w.
// Single launch: W image built in-kernel; X staged from fp32 via LDG+cvt+STS
// (LDG latency hidden under MMAs). GEMM of row n interleaved with scan of n-1.
__global__ void __launch_bounds__(512, 1)
rowlstm_fused(const float* __restrict__ x, const float* __restrict__ wgt,
              const float* __restrict__ bias, float* __restrict__ out) {
    const int tid = threadIdx.x;
    const int lane = tid & 31;
    const int wid = tid >> 5;
    const int mw = wid & 3;
    const int nw = wid >> 2;
    const int r = lane >> 2, cl = lane & 3;

    const uint32_t smb = smem_u32(smw);

    const int l7 = lane & 7, l15 = lane & 15, lk = lane >> 4;
    const int krl = l7 + ((lane & 16) >> 1);
    const int wo = (lane >> 3) & 1;

    float blo[4], bhi[4];
#pragma unroll
    for (int mt = 0; mt < 4; mt++) {
        blo[mt] = bias[mw * 64 + mt * 16 + r];
        bhi[mt] = bias[mw * 64 + mt * 16 + 8 + r];
    }
    const bool isg = (mw == 3);

    // scan mapping (row-invariant): 8 seg x 16 w, hc = tid & 63
    const int seg = tid >> 6;
    const int hc = tid & 63;
    const uint32_t gsc = smb + GATE_B + (uint32_t)hc * GROW_B + (uint32_t)seg * 32;
    const uint32_t psme = smb + PS_B + (uint32_t)(seg * 64 + hc) * 8;

// load a 96-k super-chunk (s=0/1) of row (bb_,hh_) into registers xv[6]
#define LOADX(bb_, hh_, s, xv)                                              \
    do {                                                                    \
        _Pragma("unroll") for (int t = 0; t < 3; t++) {                     \
            int g = t * 512 + tid;                                          \
            int krow = g >> 4;                                              \
            int woct = g & 15;                                              \
            int kg = (s) * 96 + krow;                                       \
            int ic = kg / 3;                                                \
            int kh = kg - 3 * ic;                                           \
            int hp = (hh_) + kh - 2;                                        \
            if (hp >= 0) {                                                  \
                const float4* p4 = reinterpret_cast<const float4*>(         \
                    x + ((size_t)(((bb_) * Cv + ic) * Hv + hp)) * Wv +      \
                    woct * 8);                                              \
                xv[2 * t] = p4[0];                                          \
                xv[2 * t + 1] = p4[1];                                      \
            } else {                                                        \
                xv[2 * t] = make_float4(0.f, 0.f, 0.f, 0.f);                \
                xv[2 * t + 1] = xv[2 * t];                                  \
            }                                                               \
        }                                                                   \
    } while (0)

// convert xv -> fp16 and store into buffer sb (same swizzled layout)
#define CVTSTS(sb, xv)                                                      \
    do {                                                                    \
        _Pragma("unroll") for (int t = 0; t < 3; t++) {                     \
            int g = t * 512 + tid;                                          \
            int krow = g >> 4;                                              \
            int woct = g & 15;                                              \
            uint32_t w0 = packh2(xv[2 * t].x, xv[2 * t].y);                 \
            uint32_t w1 = packh2(xv[2 * t].z, xv[2 * t].w);                 \
            uint32_t w2 = packh2(xv[2 * t + 1].x, xv[2 * t + 1].y);         \
            uint32_t w3 = packh2(xv[2 * t + 1].z, xv[2 * t + 1].w);         \
            uint32_t dst = smb + XBUF_B + (sb) * 24576 + krow * 256 +       \
                           ((woct ^ (krow & 7)) << 4);                      \
            asm volatile("st.shared.v4.b32 [%0], {%1,%2,%3,%4};"            \
                         :: "r"(dst), "r"(w0), "r"(w1), "r"(w2), "r"(w3)    \
                         : "memory");                                       \
        }                                                                   \
    } while (0)

// one global k-step (ksg = 0..11)
#define KSTEP(ksg, bbx)                                                     \
    do {                                                                    \
        const int loc = (ksg) % 6;                                          \
        const int chunk = (ksg) >> 2;                                       \
        const int ksin = (ksg) & 3;                                         \
        uint32_t Bh[2][4];                                                  \
        _Pragma("unroll") for (int np = 0; np < 2; np++)                    \
            LDM4T(Bh[np], (bbx)[np] + loc * 4096);                          \
        const uint32_t a_h = smb + chunk * 32768 + (mw * 64 + l15) * 128;   \
        const uint32_t swA = (uint32_t)(((2 * ksin + lk) ^ l7) << 4);       \
        _Pragma("unroll") for (int mt = 0; mt < 4; mt++) {                  \
            uint32_t A[4];                                                  \
            LDM4(A, a_h + mt * 2048 + swA);                                 \
            _Pragma("unroll") for (int nt = 0; nt < 4; nt++) {              \
                const int np = nt >> 1, ix = nt & 1;                        \
                mma_f16acc(acc[mt][nt], A, Bh[np][ix], Bh[np][2 + ix]);     \
            }                                                               \
        }                                                                   \
    } while (0)

#define SCAN_P1(j)                                                          \
    if (hasprv) {                                                           \
        uint32_t iw = lds32(gsc + 4u * (j));                                \
        uint32_t fw = lds32(gsc + 4u * (j) + 64u * GROW_B);                 \
        uint32_t gg = lds32(gsc + 4u * (j) + 192u * GROW_B);                \
        float2 iv = h2f2(iw), fv = h2f2(fw), gv = h2f2(gg);                 \
        sc = fmaf(fv.x, sc, iv.x * gv.x); sp *= fv.x;                       \
        sc = fmaf(fv.y, sc, iv.y * gv.y); sp *= fv.y;                       \
    }

#define SCAN_P3(j)                                                          \
    if (hasprv) {                                                           \
        uint32_t iw = lds32(gsc + 4u * (j));                                \
        uint32_t fw = lds32(gsc + 4u * (j) + 64u * GROW_B);                 \
        uint32_t ow = lds32(gsc + 4u * (j) + 128u * GROW_B);                \
        uint32_t gg = lds32(gsc + 4u * (j) + 192u * GROW_B);                \
        float2 iv = h2f2(iw), fv = h2f2(fw), ov = h2f2(ow), gv = h2f2(gg);  \
        c3 = fmaf(fv.x, c3, iv.x * gv.x);                                   \
        q[((j) & 1) * 2]     = ov.x * tanh_f(c3);                           \
        c3 = fmaf(fv.y, c3, iv.y * gv.y);                                   \
        q[((j) & 1) * 2 + 1] = ov.y * tanh_f(c3);                           \
        if ((j) & 1)                                                        \
            *reinterpret_cast<float4*>(po + ((j) >> 1) * 4) =               \
                make_float4(q[0], q[1], q[2], q[3]);                        \
    }

#define SCAN_P2()                                                           \
    do {                                                                    \
        cin = 0.f;                                                          \
        if (hasprv) {                                                       \
            _Pragma("unroll") for (int s2 = 0; s2 < 7; s2++) {              \
                if (s2 < seg) {                                             \
                    uint32_t psa = smb + PS_B + (uint32_t)(s2 * 64 + hc) * 8; \
                    float P, S;                                             \
                    asm volatile("ld.shared.v2.f32 {%0, %1}, [%2];"         \
                                 : "=f"(P), "=f"(S) : "r"(psa));            \
                    cin = fmaf(P, cin, S);                                  \
                }                                                           \
            }                                                               \
        }                                                                   \
    } while (0)

    // ---- preamble: build W smem image from fp32 wgt + stage first super-A
    {
        const int m = tid >> 1;
        const int kh2 = (tid & 1) * 96;
        const float4* wsrc =
            reinterpret_cast<const float4*>(wgt + m * 192 + kh2);
        const uint32_t mrow = smb + (uint32_t)m * 128;
#pragma unroll
        for (int j = 0; j < 24; j++) {
            float4 v = wsrc[j];
            int k0 = kh2 + j * 4;
            uint32_t wa = packh2(v.x, v.y);
            uint32_t wb = packh2(v.z, v.w);
            int c = k0 >> 6, kl = k0 & 63, o = kl >> 3, e = kl & 7;
            uint32_t addr = mrow + (uint32_t)(c * 32768) +
                            (uint32_t)((((o ^ (m & 7)) << 4)) + e * 2);
            sts32(addr, wa);
            sts32(addr + 4, wb);
        }
        float4 xv[6];
        LOADX(blockIdx.x >> 7, blockIdx.x & 127, 0, xv);
        CVTSTS(0, xv);
        __syncthreads();
    }

    // B fragment bases (fixed)
    uint32_t bb0[2], bb1[2];
#pragma unroll
    for (int np = 0; np < 2; np++) {
        int oct = ((nw * 32 + np * 16) >> 3) + wo;
        uint32_t sw = (uint32_t)((oct ^ l7) << 4) + (uint32_t)krl * 256;
        bb0[np] = smb + XBUF_B + sw;
        bb1[np] = smb + XBUF_B + 24576 + sw;
    }

#pragma unroll 1
    for (int bh = blockIdx.x; bh < NROWS; bh += GRID) {
        const int b = bh >> 7, h = bh & 127;
        const int nbh = bh + GRID;
        const bool hasprv = (bh != (int)blockIdx.x);
        const int pbh = bh - GRID;
        float* po = out + ((size_t)(((pbh >> 7) & 15) * HCv + hc) * Hv +
                           (pbh & 127)) * Wv + seg * 16;

        uint32_t acc[4][4][2];
#pragma unroll
        for (int mt = 0; mt < 4; mt++)
#pragma unroll
            for (int nt = 0; nt < 4; nt++) {
                acc[mt][nt][0] = 0u;
                acc[mt][nt][1] = 0u;
            }

        float sc = 0.f, sp = 1.f, c3, cin;
        float q[4];
        float4 xv[6];

        // stage super-B of this row: LDGs in flight under super-0 MMAs
        LOADX(b, h, 1, xv);

        // ---- super 0 (buf0) + scan pass1 of prev row
        KSTEP(0, bb0); SCAN_P1(0);
        KSTEP(1, bb0); SCAN_P1(1);
        KSTEP(2, bb0); SCAN_P1(2); SCAN_P1(3);
        CVTSTS(1, xv);
        KSTEP(3, bb0); SCAN_P1(4);
        KSTEP(4, bb0); SCAN_P1(5); SCAN_P1(6);
        KSTEP(5, bb0); SCAN_P1(7);

        if (hasprv)
            asm volatile("st.shared.v2.f32 [%0], {%1, %2};"
                         :: "r"(psme), "f"(sp), "f"(sc) : "memory");

        __syncthreads();   // buf0 consumed; buf1 + PS visible

        // prefetch next row's super-A: LDGs under super-1 MMAs
        if (nbh < NROWS) LOADX(nbh >> 7, nbh & 127, 0, xv);

        SCAN_P2();
        c3 = cin;

        // ---- super 1 (buf1) + scan pass3 of prev row
        KSTEP(6, bb1);  SCAN_P3(0);
        KSTEP(7, bb1);  SCAN_P3(1); SCAN_P3(2);
        KSTEP(8, bb1);  SCAN_P3(3);
        if (nbh < NROWS) CVTSTS(0, xv);
        KSTEP(9, bb1);  SCAN_P3(4); SCAN_P3(5);
        KSTEP(10, bb1); SCAN_P3(6);
        KSTEP(11, bb1); SCAN_P3(7);

        __syncthreads();   // pass3 + buf1 reads done; buf0 visible

        // ---- epilogue: unpack fp16 acc + bias + activation -> fp16 gates
#pragma unroll
        for (int mt = 0; mt < 4; mt++) {
            const uint32_t glo = smb + GATE_B +
                                 (uint32_t)(mw * 64 + mt * 16 + r) * GROW_B;
            const uint32_t ghi = glo + 8u * GROW_B;
#pragma unroll
            for (int nt = 0; nt < 4; nt++) {
                const uint32_t w2o = (uint32_t)(nw * 16 + nt * 4 + cl) * 4u;
                float2 f01 = h2f2(acc[mt][nt][0]);
                float2 f23 = h2f2(acc[mt][nt][1]);
                float v0 = f01.x + blo[mt];
                float v1 = f01.y + blo[mt];
                float v2 = f23.x + bhi[mt];
                float v3 = f23.y + bhi[mt];
                if (isg) {
                    v0 = tanh_f(v0); v1 = tanh_f(v1);
                    v2 = tanh_f(v2); v3 = tanh_f(v3);
                } else {
                    v0 = sigmoid_f(v0); v1 = sigmoid_f(v1);
                    v2 = sigmoid_f(v2); v3 = sigmoid_f(v3);
                }
                sts32(glo + w2o, packh2(v0, v1));
                sts32(ghi + w2o, packh2(v2, v3));
            }
        }
        __syncthreads();   // gates visible for next iter's pass1
    }

    // ---- tail: scan of the last row (non-interleaved)
    {
        const bool hasprv = true;
        const int lbh = (int)blockIdx.x +
                        ((NROWS - 1 - (int)blockIdx.x) / GRID) * GRID;
        float* po = out + ((size_t)(((lbh >> 7) & 15) * HCv + hc) * Hv +
                           (lbh & 127)) * Wv + seg * 16;
        float sc = 0.f, sp = 1.f, c3, cin;
        float q[4];
        SCAN_P1(0); SCAN_P1(1); SCAN_P1(2); SCAN_P1(3);
        SCAN_P1(4); SCAN_P1(5); SCAN_P1(6); SCAN_P1(7);
        asm volatile("st.shared.v2.f32 [%0], {%1, %2};"
                     :: "r"(psme), "f"(sp), "f"(sc) : "memory");
        __syncthreads();
        SCAN_P2();
        c3 = cin;
        SCAN_P3(0); SCAN_P3(1); SCAN_P3(2); SCAN_P3(3);
        SCAN_P3(4); SCAN_P3(5); SCAN_P3(6); SCAN_P3(7);
    }
}

extern "C" void kernel_launch(void* const* d_in, const int* in_sizes, int n_in,
                              void* d_out, int out_size) {
    const float* x    = (const float*)d_in[0];
    const float* wgt  = (const float*)d_in[1];
    const float* bias = (const float*)d_in[2];
    float* out = (float*)d_out;

    cudaFuncSetAttribute(rowlstm_fused,
                         cudaFuncAttributeMaxDynamicSharedMemorySize, SMEM_BYTES);

    rowlstm_fused<<<GRID, 512, SMEM_BYTES>>>(x, wgt, bias, out);
}